// round 13
// baseline (speedup 1.0000x reference)
#include <cuda_runtime.h>
#include <cuda_bf16.h>
#include <stdint.h>
#include <math.h>

#define BB   4
#define CIN  128
#define COUT 128
#define HH   128
#define WW   128
#define HW   (HH*WW)

// ---------------- global scratch ----------------
__device__ float g_nhwc[BB*HW*CIN];                        // inp NHWC fp32
__device__ float g_off [BB*HW*27];                         // py[9], px[9], mask[9]
__device__ __align__(16) __nv_bfloat16 g_fh[BB*HW*CIN];    // feat NHWC bf16 hi
__device__ __align__(16) __nv_bfloat16 g_fl[BB*HW*CIN];    // feat NHWC bf16 lo
__device__ __align__(16) __nv_bfloat16 g_wtA[9*2*16384];   // per tap: swizzled [co][ci] hi+lo (deform A)
__device__ __align__(16) __nv_bfloat16 g_woffA[9*2*4096];  // per tap: swizzled [32oc pad][ci] hi+lo (offset A)

// ---------------- helpers ----------------
__device__ __forceinline__ uint32_t smem_u32(const void* p) {
    uint32_t a;
    asm("{ .reg .u64 t; cvta.to.shared.u64 t, %1; cvt.u32.u64 %0, t; }" : "=r"(a) : "l"(p));
    return a;
}
__device__ __forceinline__ void ldmx4(uint32_t* r, uint32_t addr) {
    asm volatile("ldmatrix.sync.aligned.m8n8.x4.shared.b16 {%0,%1,%2,%3}, [%4];"
        : "=r"(r[0]), "=r"(r[1]), "=r"(r[2]), "=r"(r[3]) : "r"(addr));
}
__device__ __forceinline__ void mma_bf16(float* d, const uint32_t* a, const uint32_t* b) {
    asm volatile("mma.sync.aligned.m16n8k16.row.col.f32.bf16.bf16.f32 "
        "{%0,%1,%2,%3}, {%4,%5,%6,%7}, {%8,%9}, {%0,%1,%2,%3};"
        : "+f"(d[0]), "+f"(d[1]), "+f"(d[2]), "+f"(d[3])
        : "r"(a[0]), "r"(a[1]), "r"(a[2]), "r"(a[3]), "r"(b[0]), "r"(b[1]));
}
__device__ __forceinline__ void cpasync16(uint32_t dst, const void* src) {
    asm volatile("cp.async.cg.shared.global [%0], [%1], 16;" :: "r"(dst), "l"(src));
}
#define CPASYNC_WAIT() asm volatile("cp.async.wait_all;" ::: "memory")

__device__ __forceinline__ void fma2(unsigned long long &d, unsigned long long a, unsigned long long b) {
    asm("fma.rn.f32x2 %0, %1, %2, %0;" : "+l"(d) : "l"(a), "l"(b));
}
__device__ __forceinline__ unsigned long long dup2(float x) {
    unsigned long long r; asm("mov.b64 %0, {%1, %1};" : "=l"(r) : "f"(x)); return r;
}
__device__ __forceinline__ float2 unpk(unsigned long long v) {
    float2 r; asm("mov.b64 {%0, %1}, %2;" : "=f"(r.x), "=f"(r.y) : "l"(v)); return r;
}
// packs: a -> upper 16, b -> lower 16
__device__ __forceinline__ uint32_t cvt_bf2(float hi, float lo) {
    uint32_t d; asm("cvt.rn.bf16x2.f32 %0, %1, %2;" : "=r"(d) : "f"(hi), "f"(lo)); return d;
}

// swizzled byte offset in a [rows][128 cols-bf16] tile, pitch 256 B
__device__ __forceinline__ uint32_t tswz(int row, int ci) {
    return (uint32_t)(row * 256 + ((((ci >> 3) ^ (row & 7)) << 4) | ((ci & 7) * 2)));
}

// ---------------- Kernel: NCHW -> NHWC fp32 transpose of inp ----------------
__global__ void k_transpose(const float* __restrict__ inp) {
    __shared__ float tile[32][33];
    int b = blockIdx.z, c0 = blockIdx.y * 32, p0 = blockIdx.x * 32;
    int tx = threadIdx.x, ty = threadIdx.y;
#pragma unroll
    for (int i = 0; i < 4; i++)
        tile[ty + i * 8][tx] = inp[(b * CIN + c0 + ty + i * 8) * HW + p0 + tx];
    __syncthreads();
#pragma unroll
    for (int i = 0; i < 4; i++)
        g_nhwc[((size_t)b * HW + p0 + ty + i * 8) * CIN + c0 + tx] = tile[tx][ty + i * 8];
}

// ---------------- Kernel: NCHW -> NHWC bf16 hi/lo transpose of feat ----------------
__global__ void k_transposeF(const float* __restrict__ feat) {
    __shared__ float tile[32][33];
    int b = blockIdx.z, c0 = blockIdx.y * 32, p0 = blockIdx.x * 32;
    int tx = threadIdx.x, ty = threadIdx.y;
#pragma unroll
    for (int i = 0; i < 4; i++)
        tile[ty + i * 8][tx] = feat[(b * CIN + c0 + ty + i * 8) * HW + p0 + tx];
    __syncthreads();
#pragma unroll
    for (int i = 0; i < 4; i++) {
        float w = tile[tx][ty + i * 8];
        __nv_bfloat16 h = __float2bfloat16(w);
        __nv_bfloat16 l = __float2bfloat16(w - __bfloat162float(h));
        size_t idx = ((size_t)b * HW + p0 + ty + i * 8) * CIN + c0 + tx;
        g_fh[idx] = h;
        g_fl[idx] = l;
    }
}

// ---------------- Kernel: w_dc -> swizzled bf16 hi/lo A tiles [co][ci] ----------------
__global__ void k_prep_wtA(const float* __restrict__ w_dc) {
    int idx = blockIdx.x * blockDim.x + threadIdx.x;
    if (idx >= 9 * 16384) return;
    int t  = idx >> 14;
    int r  = idx & 16383;
    int co = r >> 7;
    int ci = r & 127;
    float w = w_dc[(co * CIN + ci) * 9 + t];
    __nv_bfloat16 h = __float2bfloat16(w);
    __nv_bfloat16 l = __float2bfloat16(w - __bfloat162float(h));
    uint32_t e = tswz(co, ci) >> 1;
    g_wtA[t * 32768 + e]         = h;
    g_wtA[t * 32768 + 16384 + e] = l;
}

// ---------------- Kernel: w_off -> swizzled bf16 hi/lo A tiles [32oc pad][ci] ----------------
__global__ void k_prep_woffA(const float* __restrict__ w_off) {
    int idx = blockIdx.x * blockDim.x + threadIdx.x;
    if (idx >= 9 * 4096) return;
    int t  = idx >> 12;
    int r  = idx & 4095;
    int oc = r >> 7;
    int ci = r & 127;
    float w = (oc < 27) ? w_off[(oc * CIN + ci) * 9 + t] : 0.f;
    __nv_bfloat16 h = __float2bfloat16(w);
    __nv_bfloat16 l = __float2bfloat16(w - __bfloat162float(h));
    uint32_t e = tswz(oc, ci) >> 1;
    g_woffA[t * 8192 + e]        = h;
    g_woffA[t * 8192 + 4096 + e] = l;
}

// ---------------- Kernel: offset conv via mma.sync (unchanged, verified) ----------------
#define OC_A    0
#define OC_B    16384
#define OC_RAW  81920
#define OC_SMEM (OC_RAW + 128*33*4)

__global__ __launch_bounds__(256) void k_offset_tc(const float* __restrict__ b_off) {
    extern __shared__ __align__(1024) char smem[];
    const uint32_t sbase = smem_u32(smem);
    const int tid = threadIdx.x, lane = tid & 31, warp = tid >> 5;
    const int b = blockIdx.x >> 7, y = blockIdx.x & 127;

    const int sub = lane >> 3, lr = lane & 7;
    const int kxa = sub >> 1, kxb = sub & 1;
    const int n0 = warp * 16;
    const uint32_t aoA0 = (uint32_t)((sub & 1) * 8 + lr) * 256;
    const uint32_t aoA1 = aoA0 + 16 * 256;
    const uint32_t boff = (uint32_t)(n0 + (sub >> 1) * 8 + lr) * 256;
    const uint32_t sAh = sbase + OC_A, sAl = sAh + 8192;
    const uint32_t sBh = sbase + OC_B, sBl = sBh + 32768;

    const int sp = tid >> 1, ci0 = (tid & 1) * 64;

    float acco[2][2][4];
#pragma unroll
    for (int i = 0; i < 2; i++)
#pragma unroll
        for (int j = 0; j < 2; j++)
#pragma unroll
            for (int k = 0; k < 4; k++) acco[i][j][k] = 0.f;

    for (int t = 0; t < 9; t++) {
        __syncthreads();
        {
            const char* src = (const char*)(g_woffA + (size_t)t * 8192);
#pragma unroll
            for (int e = 0; e < 4; e++)
                cpasync16(sbase + OC_A + (uint32_t)(tid + e * 256) * 16, src + (size_t)(tid + e * 256) * 16);
        }
        {
            int ky = t / 3, kx = t - ky * 3;
            int yy = y + ky - 1, xx = sp + kx - 1;
            bool ok = (yy >= 0) & (yy < HH) & (xx >= 0) & (xx < WW);
            int yyc = min(max(yy, 0), HH - 1), xxc = min(max(xx, 0), WW - 1);
            size_t pbase = ((size_t)(b * HW + yyc * WW + xxc)) * CIN + ci0;
            const uint4* fh = (const uint4*)(g_fh + pbase);
            const uint4* fl = (const uint4*)(g_fl + pbase);
            const uint4 z4 = make_uint4(0, 0, 0, 0);
#pragma unroll
            for (int j = 0; j < 8; j++) {
                uint4 vh = ok ? fh[j] : z4;
                uint4 vl = ok ? fl[j] : z4;
                uint32_t a0 = tswz(sp, ci0 + 8 * j);
                *(uint4*)(smem + OC_B + a0)         = vh;
                *(uint4*)(smem + OC_B + 32768 + a0) = vl;
            }
        }
        CPASYNC_WAIT();
        __syncthreads();

#pragma unroll
        for (int ks = 0; ks < 8; ks++) {
            uint32_t ca = (uint32_t)(((2 * ks + kxa) ^ lr) << 4);
            uint32_t cb = (uint32_t)(((2 * ks + kxb) ^ lr) << 4);
            uint32_t ah0[4], ah1[4], al0[4], al1[4];
            ldmx4(ah0, sAh + aoA0 + ca);
            ldmx4(ah1, sAh + aoA1 + ca);
            ldmx4(al0, sAl + aoA0 + ca);
            ldmx4(al1, sAl + aoA1 + ca);
            uint32_t qh[4], ql[4];
            ldmx4(qh, sBh + boff + cb);
            ldmx4(ql, sBl + boff + cb);
            uint32_t bh[2][2] = { { qh[0], qh[1] }, { qh[2], qh[3] } };
            uint32_t bl[2][2] = { { ql[0], ql[1] }, { ql[2], ql[3] } };
#pragma unroll
            for (int nt = 0; nt < 2; nt++) {
                mma_bf16(acco[0][nt], ah0, bh[nt]);
                mma_bf16(acco[1][nt], ah1, bh[nt]);
                mma_bf16(acco[0][nt], al0, bh[nt]);
                mma_bf16(acco[1][nt], al1, bh[nt]);
                mma_bf16(acco[0][nt], ah0, bl[nt]);
                mma_bf16(acco[1][nt], ah1, bl[nt]);
            }
        }
    }

    float* raw = (float*)(smem + OC_RAW);
    const int g = lane >> 2, tig = lane & 3;
#pragma unroll
    for (int mt = 0; mt < 2; mt++)
#pragma unroll
        for (int nt = 0; nt < 2; nt++) {
            int r0 = mt * 16 + g;
            int px0 = n0 + nt * 8 + 2 * tig;
            raw[px0 * 33 + r0]           = acco[mt][nt][0];
            raw[(px0 + 1) * 33 + r0]     = acco[mt][nt][1];
            raw[px0 * 33 + r0 + 8]       = acco[mt][nt][2];
            raw[(px0 + 1) * 33 + r0 + 8] = acco[mt][nt][3];
        }
    __syncthreads();
    if (tid < 128) {
        int px = tid;
        float a[27];
#pragma unroll
        for (int k = 0; k < 27; k++) a[k] = raw[px * 33 + k] + b_off[k];
        float* o = &g_off[((size_t)(b * HH + y) * WW + px) * 27];
#pragma unroll
        for (int k = 0; k < 9; k++) {
            int ky = k / 3, kx = k - ky * 3;
            o[k]      = a[2 * k]     + (float)(y + ky - 1);
            o[9 + k]  = a[2 * k + 1] + (float)(px + kx - 1);
            o[18 + k] = 1.f / (1.f + __expf(-a[18 + k]));
        }
    }
}

// ---------------- Kernel: warp-specialized deform GEMM v2 ----------------
// 512 threads: warps 0-7 consumers (R11 4x2 grid, 32co x 32px tiles) + A staging,
//              warps 8-15 samplers (pure bilinear).
// smem: A[2] 2x64K | B[2] 2x32K = 192 KB, 1 block/SM.
#define OFF_A   0
#define OFF_B   131072
#define SMEM_BYTES 196608

__global__ __launch_bounds__(512) void k_main(const float* __restrict__ b_dc,
                                              float* __restrict__ out) {
    extern __shared__ __align__(1024) char smem[];
    const uint32_t sbase = smem_u32(smem);
    const int tid = threadIdx.x, lane = tid & 31, warp = tid >> 5;
    const int b = blockIdx.x >> 8;
    const int rem = blockIdx.x & 255;
    const int y = rem >> 1;
    const int px0 = (rem & 1) * 64;

    const int sub = lane >> 3, lr = lane & 7;
    const int kxa = sub >> 1, kxb = sub & 1;

    // --- consumer state (warps 0-7): R11 geometry, 4x2 grid, 32co x 32px ---
    const int mrow = (warp & 3) * 32;
    const int ncol = (warp >> 2) * 32;          // 0 or 32 for warps 0-7
    const uint32_t aoff0 = (uint32_t)(mrow + (sub & 1) * 8 + lr) * 256;
    const uint32_t aoff1 = aoff0 + 16 * 256;
    const uint32_t boff0 = (uint32_t)(ncol + (sub >> 1) * 8 + lr) * 256;
    const uint32_t boff1 = boff0 + 16 * 256;

    // --- sampler state (warps 8-15) ---
    const int stid = tid - 256;                 // 0..255 for samplers
    const int sp   = (stid >= 0 ? stid : 0) >> 2;
    const int ci0  = ((stid >= 0 ? stid : 0) & 3) * 32;
    const float* ofs    = &g_off[((size_t)(b * HH + y) * WW + px0 + sp) * 27];
    const float* base_b = g_nhwc + (size_t)b * HW * CIN;

    float acc[2][4][4];
    if (warp < 8) {
#pragma unroll
        for (int i = 0; i < 2; i++)
#pragma unroll
            for (int j = 0; j < 4; j++)
#pragma unroll
                for (int k = 0; k < 4; k++) acc[i][j][k] = 0.f;
    }

    // sampler bilinear fill of B[BUF] for tap TT (pure; no cp.async)
#define STAGE_B(TT, BUF) do {                                                               \
        float py = ofs[TT], pxx = ofs[9 + (TT)], m = ofs[18 + (TT)];                        \
        float y0f = floorf(py), x0f = floorf(pxx);                                          \
        float ly = py - y0f, lx = pxx - x0f;                                                \
        int y0 = (int)y0f, x0 = (int)x0f, y1 = y0 + 1, x1 = x0 + 1;                         \
        float f00 = (y0 >= 0 && y0 < HH && x0 >= 0 && x0 < WW) ? 1.f : 0.f;                 \
        float f01 = (y0 >= 0 && y0 < HH && x1 >= 0 && x1 < WW) ? 1.f : 0.f;                 \
        float f10 = (y1 >= 0 && y1 < HH && x0 >= 0 && x0 < WW) ? 1.f : 0.f;                 \
        float f11 = (y1 >= 0 && y1 < HH && x1 >= 0 && x1 < WW) ? 1.f : 0.f;                 \
        const unsigned long long w00d = dup2((1.f - ly) * (1.f - lx) * m * f00);            \
        const unsigned long long w01d = dup2((1.f - ly) * lx         * m * f01);            \
        const unsigned long long w10d = dup2(ly         * (1.f - lx) * m * f10);            \
        const unsigned long long w11d = dup2(ly         * lx         * m * f11);            \
        int y0c = min(max(y0, 0), HH - 1), x0c = min(max(x0, 0), WW - 1);                   \
        int y1c = min(max(y1, 0), HH - 1), x1c = min(max(x1, 0), WW - 1);                   \
        const float* r00 = base_b + ((size_t)(y0c * WW + x0c)) * CIN;                       \
        const float* r01 = base_b + ((size_t)(y0c * WW + x1c)) * CIN;                       \
        const float* r10 = base_b + ((size_t)(y1c * WW + x0c)) * CIN;                       \
        const float* r11 = base_b + ((size_t)(y1c * WW + x1c)) * CIN;                       \
        _Pragma("unroll")                                                                   \
        for (int i = 0; i < 8; i++) {                                                       \
            int ci = ci0 + i * 4;                                                           \
            ulonglong2 A2 = *(const ulonglong2*)(r00 + ci);                                 \
            ulonglong2 C2 = *(const ulonglong2*)(r01 + ci);                                 \
            ulonglong2 D2 = *(const ulonglong2*)(r10 + ci);                                 \
            ulonglong2 E2 = *(const ulonglong2*)(r11 + ci);                                 \
            unsigned long long v01 = 0ULL, v23 = 0ULL;                                      \
            fma2(v01, A2.x, w00d); fma2(v01, C2.x, w01d); fma2(v01, D2.x, w10d); fma2(v01, E2.x, w11d); \
            fma2(v23, A2.y, w00d); fma2(v23, C2.y, w01d); fma2(v23, D2.y, w10d); fma2(v23, E2.y, w11d); \
            float2 f01v = unpk(v01), f23v = unpk(v23);                                      \
            uint32_t hi01 = cvt_bf2(f01v.y, f01v.x);                                       \
            uint32_t hi23 = cvt_bf2(f23v.y, f23v.x);                                       \
            float l0 = f01v.x - __uint_as_float(hi01 << 16);                                \
            float l1 = f01v.y - __uint_as_float(hi01 & 0xFFFF0000u);                        \
            float l2 = f23v.x - __uint_as_float(hi23 << 16);                                \
            float l3 = f23v.y - __uint_as_float(hi23 & 0xFFFF0000u);                        \
            uint32_t lo01 = cvt_bf2(l1, l0);                                                \
            uint32_t lo23 = cvt_bf2(l3, l2);                                                \
            uint32_t a0 = tswz(sp, ci);                                                     \
            *(unsigned long long*)(smem + OFF_B + (BUF) * 32768 + a0)         = ((unsigned long long)hi23 << 32) | hi01; \
            *(unsigned long long*)(smem + OFF_B + (BUF) * 32768 + 16384 + a0) = ((unsigned long long)lo23 << 32) | lo01; \
        }                                                                                   \
    } while (0)

    // consumer A-staging: 64KB into A[BUF], 256 consumer threads x 16 chunks
#define STAGE_A(TT, BUF) do {                                                               \
        const char* asrc = (const char*)(g_wtA + (size_t)(TT) * 32768);                     \
        uint32_t adst = sbase + OFF_A + (uint32_t)(BUF) * 65536;                            \
        _Pragma("unroll")                                                                   \
        for (int e = 0; e < 16; e++)                                                        \
            cpasync16(adst + (uint32_t)(tid + e * 256) * 16, asrc + (size_t)(tid + e * 256) * 16); \
    } while (0)

    // prologue: consumers stage A[0]; samplers fill B[0]
    if (warp < 8) {
        STAGE_A(0, 0);
        CPASYNC_WAIT();
    } else {
        STAGE_B(0, 0);
    }
    __syncthreads();

    for (int t = 0; t < 9; t++) {
        const int cur = t & 1;
        if (warp < 8) {
            if (t < 8) STAGE_A(t + 1, (t + 1) & 1);   // hides behind GEMM below
            const uint32_t sAh = sbase + OFF_A + (uint32_t)cur * 65536;
            const uint32_t sAl = sAh + 32768;
            const uint32_t sBh = sbase + OFF_B + (uint32_t)cur * 32768;
            const uint32_t sBl = sBh + 16384;
#pragma unroll
            for (int ks = 0; ks < 8; ks++) {
                uint32_t ca = (uint32_t)(((2 * ks + kxa) ^ lr) << 4);
                uint32_t cb = (uint32_t)(((2 * ks + kxb) ^ lr) << 4);
                uint32_t ah0[4], ah1[4], al0[4], al1[4];
                ldmx4(ah0, sAh + aoff0 + ca);
                ldmx4(ah1, sAh + aoff1 + ca);
                ldmx4(al0, sAl + aoff0 + ca);
                ldmx4(al1, sAl + aoff1 + ca);
                uint32_t bh[4][2], bl[4][2], q[4];
                ldmx4(q, sBh + boff0 + cb); bh[0][0]=q[0]; bh[0][1]=q[1]; bh[1][0]=q[2]; bh[1][1]=q[3];
                ldmx4(q, sBh + boff1 + cb); bh[2][0]=q[0]; bh[2][1]=q[1]; bh[3][0]=q[2]; bh[3][1]=q[3];
                ldmx4(q, sBl + boff0 + cb); bl[0][0]=q[0]; bl[0][1]=q[1]; bl[1][0]=q[2]; bl[1][1]=q[3];
                ldmx4(q, sBl + boff1 + cb); bl[2][0]=q[0]; bl[2][1]=q[1]; bl[3][0]=q[2]; bl[3][1]=q[3];
#pragma unroll
                for (int nt = 0; nt < 4; nt++) {
                    mma_bf16(acc[0][nt], ah0, bh[nt]);
                    mma_bf16(acc[1][nt], ah1, bh[nt]);
                    mma_bf16(acc[0][nt], al0, bh[nt]);
                    mma_bf16(acc[1][nt], al1, bh[nt]);
                    mma_bf16(acc[0][nt], ah0, bl[nt]);
                    mma_bf16(acc[1][nt], ah1, bl[nt]);
                }
            }
            if (t < 8) CPASYNC_WAIT();
        } else if (t < 8) {
            STAGE_B(t + 1, (t + 1) & 1);
        }
        __syncthreads();
    }

    // epilogue: consumers write d-frags -> gmem NCHW with bias (R11 layout)
    if (warp < 8) {
        const int g = lane >> 2, tig = lane & 3;
#pragma unroll
        for (int mt = 0; mt < 2; mt++) {
            int coA = mrow + mt * 16 + g;
            int coB = coA + 8;
            float bA = b_dc[coA], bB2 = b_dc[coB];
            float* oA = out + ((size_t)(b * COUT + coA) * HH + y) * WW + px0;
            float* oB = out + ((size_t)(b * COUT + coB) * HH + y) * WW + px0;
#pragma unroll
            for (int nt = 0; nt < 4; nt++) {
                int px = ncol + nt * 8 + 2 * tig;
                float2 vA = make_float2(acc[mt][nt][0] + bA,  acc[mt][nt][1] + bA);
                float2 vB = make_float2(acc[mt][nt][2] + bB2, acc[mt][nt][3] + bB2);
                *(float2*)(oA + px) = vA;
                *(float2*)(oB + px) = vB;
            }
        }
    }
#undef STAGE_B
#undef STAGE_A
}

// ---------------- launch ----------------
extern "C" void kernel_launch(void* const* d_in, const int* in_sizes, int n_in,
                              void* d_out, int out_size) {
    const float* inp   = (const float*)d_in[0];
    const float* feat  = (const float*)d_in[1];
    const float* w_off = (const float*)d_in[2];
    const float* b_off = (const float*)d_in[3];
    const float* w_dc  = (const float*)d_in[4];
    const float* b_dc  = (const float*)d_in[5];
    float* out = (float*)d_out;

    static bool attr_set = false;
    if (!attr_set) {
        cudaFuncSetAttribute(k_main, cudaFuncAttributeMaxDynamicSharedMemorySize, SMEM_BYTES);
        cudaFuncSetAttribute(k_offset_tc, cudaFuncAttributeMaxDynamicSharedMemorySize, OC_SMEM);
        attr_set = true;
    }

    k_transposeF<<<dim3(HW / 32, CIN / 32, BB), dim3(32, 8)>>>(feat);
    k_prep_woffA<<<(9 * 4096 + 255) / 256, 256>>>(w_off);
    k_transpose<<<dim3(HW / 32, CIN / 32, BB), dim3(32, 8)>>>(inp);
    k_prep_wtA<<<(9 * 16384 + 255) / 256, 256>>>(w_dc);
    k_offset_tc<<<BB * HH, 256, OC_SMEM>>>(b_off);
    k_main<<<BB * HH * 2, 512, SMEM_BYTES>>>(b_dc, out);
}

// round 14
// speedup vs baseline: 1.4293x; 1.4293x over previous
#include <cuda_runtime.h>
#include <cuda_bf16.h>
#include <stdint.h>
#include <math.h>

#define BB   4
#define CIN  128
#define COUT 128
#define HH   128
#define WW   128
#define HW   (HH*WW)

// ---------------- global scratch ----------------
__device__ float g_nhwc[BB*HW*CIN];                        // inp NHWC fp32
__device__ float g_off [BB*HW*27];                         // py[9], px[9], mask[9]
__device__ __align__(16) __nv_bfloat16 g_fh[BB*HW*CIN];    // feat NHWC bf16 hi
__device__ __align__(16) __nv_bfloat16 g_fl[BB*HW*CIN];    // feat NHWC bf16 lo
__device__ __align__(16) __nv_bfloat16 g_wtA[9*2*16384];   // per tap: swizzled [co][ci] hi+lo (deform A)
__device__ __align__(16) __nv_bfloat16 g_woffA[9*2*4096];  // per tap: swizzled [32oc pad][ci] hi+lo (offset A)

// ---------------- helpers ----------------
__device__ __forceinline__ uint32_t smem_u32(const void* p) {
    uint32_t a;
    asm("{ .reg .u64 t; cvta.to.shared.u64 t, %1; cvt.u32.u64 %0, t; }" : "=r"(a) : "l"(p));
    return a;
}
__device__ __forceinline__ void ldmx4(uint32_t* r, uint32_t addr) {
    asm volatile("ldmatrix.sync.aligned.m8n8.x4.shared.b16 {%0,%1,%2,%3}, [%4];"
        : "=r"(r[0]), "=r"(r[1]), "=r"(r[2]), "=r"(r[3]) : "r"(addr));
}
__device__ __forceinline__ void mma_bf16(float* d, const uint32_t* a, const uint32_t* b) {
    asm volatile("mma.sync.aligned.m16n8k16.row.col.f32.bf16.bf16.f32 "
        "{%0,%1,%2,%3}, {%4,%5,%6,%7}, {%8,%9}, {%0,%1,%2,%3};"
        : "+f"(d[0]), "+f"(d[1]), "+f"(d[2]), "+f"(d[3])
        : "r"(a[0]), "r"(a[1]), "r"(a[2]), "r"(a[3]), "r"(b[0]), "r"(b[1]));
}
__device__ __forceinline__ void cpasync16(uint32_t dst, const void* src) {
    asm volatile("cp.async.cg.shared.global [%0], [%1], 16;" :: "r"(dst), "l"(src));
}
#define CPASYNC_WAIT() asm volatile("cp.async.wait_all;" ::: "memory")

__device__ __forceinline__ void fma2(unsigned long long &d, unsigned long long a, unsigned long long b) {
    asm("fma.rn.f32x2 %0, %1, %2, %0;" : "+l"(d) : "l"(a), "l"(b));
}
__device__ __forceinline__ unsigned long long dup2(float x) {
    unsigned long long r; asm("mov.b64 %0, {%1, %1};" : "=l"(r) : "f"(x)); return r;
}
__device__ __forceinline__ float2 unpk(unsigned long long v) {
    float2 r; asm("mov.b64 {%0, %1}, %2;" : "=f"(r.x), "=f"(r.y) : "l"(v)); return r;
}
// packs: a -> upper 16, b -> lower 16
__device__ __forceinline__ uint32_t cvt_bf2(float hi, float lo) {
    uint32_t d; asm("cvt.rn.bf16x2.f32 %0, %1, %2;" : "=r"(d) : "f"(hi), "f"(lo)); return d;
}

// swizzled byte offset in a [rows][128 cols-bf16] tile, pitch 256 B
__device__ __forceinline__ uint32_t tswz(int row, int ci) {
    return (uint32_t)(row * 256 + ((((ci >> 3) ^ (row & 7)) << 4) | ((ci & 7) * 2)));
}

// ---------------- Kernel: NCHW -> NHWC fp32 transpose of inp ----------------
__global__ void k_transpose(const float* __restrict__ inp) {
    __shared__ float tile[32][33];
    int b = blockIdx.z, c0 = blockIdx.y * 32, p0 = blockIdx.x * 32;
    int tx = threadIdx.x, ty = threadIdx.y;
#pragma unroll
    for (int i = 0; i < 4; i++)
        tile[ty + i * 8][tx] = inp[(b * CIN + c0 + ty + i * 8) * HW + p0 + tx];
    __syncthreads();
#pragma unroll
    for (int i = 0; i < 4; i++)
        g_nhwc[((size_t)b * HW + p0 + ty + i * 8) * CIN + c0 + tx] = tile[tx][ty + i * 8];
}

// ---------------- Kernel: NCHW -> NHWC bf16 hi/lo transpose of feat ----------------
__global__ void k_transposeF(const float* __restrict__ feat) {
    __shared__ float tile[32][33];
    int b = blockIdx.z, c0 = blockIdx.y * 32, p0 = blockIdx.x * 32;
    int tx = threadIdx.x, ty = threadIdx.y;
#pragma unroll
    for (int i = 0; i < 4; i++)
        tile[ty + i * 8][tx] = feat[(b * CIN + c0 + ty + i * 8) * HW + p0 + tx];
    __syncthreads();
#pragma unroll
    for (int i = 0; i < 4; i++) {
        float w = tile[tx][ty + i * 8];
        __nv_bfloat16 h = __float2bfloat16(w);
        __nv_bfloat16 l = __float2bfloat16(w - __bfloat162float(h));
        size_t idx = ((size_t)b * HW + p0 + ty + i * 8) * CIN + c0 + tx;
        g_fh[idx] = h;
        g_fl[idx] = l;
    }
}

// ---------------- Kernel: w_dc -> swizzled bf16 hi/lo A tiles [co][ci] ----------------
__global__ void k_prep_wtA(const float* __restrict__ w_dc) {
    int idx = blockIdx.x * blockDim.x + threadIdx.x;
    if (idx >= 9 * 16384) return;
    int t  = idx >> 14;
    int r  = idx & 16383;
    int co = r >> 7;
    int ci = r & 127;
    float w = w_dc[(co * CIN + ci) * 9 + t];
    __nv_bfloat16 h = __float2bfloat16(w);
    __nv_bfloat16 l = __float2bfloat16(w - __bfloat162float(h));
    uint32_t e = tswz(co, ci) >> 1;
    g_wtA[t * 32768 + e]         = h;
    g_wtA[t * 32768 + 16384 + e] = l;
}

// ---------------- Kernel: w_off -> swizzled bf16 hi/lo A tiles [32oc pad][ci] ----------------
__global__ void k_prep_woffA(const float* __restrict__ w_off) {
    int idx = blockIdx.x * blockDim.x + threadIdx.x;
    if (idx >= 9 * 4096) return;
    int t  = idx >> 12;
    int r  = idx & 4095;
    int oc = r >> 7;
    int ci = r & 127;
    float w = (oc < 27) ? w_off[(oc * CIN + ci) * 9 + t] : 0.f;
    __nv_bfloat16 h = __float2bfloat16(w);
    __nv_bfloat16 l = __float2bfloat16(w - __bfloat162float(h));
    uint32_t e = tswz(oc, ci) >> 1;
    g_woffA[t * 8192 + e]        = h;
    g_woffA[t * 8192 + 4096 + e] = l;
}

// ---------------- Kernel: offset conv via mma.sync (unchanged, verified) ----------------
#define OC_A    0
#define OC_B    16384
#define OC_RAW  81920
#define OC_SMEM (OC_RAW + 128*33*4)

__global__ __launch_bounds__(256) void k_offset_tc(const float* __restrict__ b_off) {
    extern __shared__ __align__(1024) char smem[];
    const uint32_t sbase = smem_u32(smem);
    const int tid = threadIdx.x, lane = tid & 31, warp = tid >> 5;
    const int b = blockIdx.x >> 7, y = blockIdx.x & 127;

    const int sub = lane >> 3, lr = lane & 7;
    const int kxa = sub >> 1, kxb = sub & 1;
    const int n0 = warp * 16;
    const uint32_t aoA0 = (uint32_t)((sub & 1) * 8 + lr) * 256;
    const uint32_t aoA1 = aoA0 + 16 * 256;
    const uint32_t boff = (uint32_t)(n0 + (sub >> 1) * 8 + lr) * 256;
    const uint32_t sAh = sbase + OC_A, sAl = sAh + 8192;
    const uint32_t sBh = sbase + OC_B, sBl = sBh + 32768;

    const int sp = tid >> 1, ci0 = (tid & 1) * 64;

    float acco[2][2][4];
#pragma unroll
    for (int i = 0; i < 2; i++)
#pragma unroll
        for (int j = 0; j < 2; j++)
#pragma unroll
            for (int k = 0; k < 4; k++) acco[i][j][k] = 0.f;

    for (int t = 0; t < 9; t++) {
        __syncthreads();
        {
            const char* src = (const char*)(g_woffA + (size_t)t * 8192);
#pragma unroll
            for (int e = 0; e < 4; e++)
                cpasync16(sbase + OC_A + (uint32_t)(tid + e * 256) * 16, src + (size_t)(tid + e * 256) * 16);
        }
        {
            int ky = t / 3, kx = t - ky * 3;
            int yy = y + ky - 1, xx = sp + kx - 1;
            bool ok = (yy >= 0) & (yy < HH) & (xx >= 0) & (xx < WW);
            int yyc = min(max(yy, 0), HH - 1), xxc = min(max(xx, 0), WW - 1);
            size_t pbase = ((size_t)(b * HW + yyc * WW + xxc)) * CIN + ci0;
            const uint4* fh = (const uint4*)(g_fh + pbase);
            const uint4* fl = (const uint4*)(g_fl + pbase);
            const uint4 z4 = make_uint4(0, 0, 0, 0);
#pragma unroll
            for (int j = 0; j < 8; j++) {
                uint4 vh = ok ? fh[j] : z4;
                uint4 vl = ok ? fl[j] : z4;
                uint32_t a0 = tswz(sp, ci0 + 8 * j);
                *(uint4*)(smem + OC_B + a0)         = vh;
                *(uint4*)(smem + OC_B + 32768 + a0) = vl;
            }
        }
        CPASYNC_WAIT();
        __syncthreads();

#pragma unroll
        for (int ks = 0; ks < 8; ks++) {
            uint32_t ca = (uint32_t)(((2 * ks + kxa) ^ lr) << 4);
            uint32_t cb = (uint32_t)(((2 * ks + kxb) ^ lr) << 4);
            uint32_t ah0[4], ah1[4], al0[4], al1[4];
            ldmx4(ah0, sAh + aoA0 + ca);
            ldmx4(ah1, sAh + aoA1 + ca);
            ldmx4(al0, sAl + aoA0 + ca);
            ldmx4(al1, sAl + aoA1 + ca);
            uint32_t qh[4], ql[4];
            ldmx4(qh, sBh + boff + cb);
            ldmx4(ql, sBl + boff + cb);
            uint32_t bh[2][2] = { { qh[0], qh[1] }, { qh[2], qh[3] } };
            uint32_t bl[2][2] = { { ql[0], ql[1] }, { ql[2], ql[3] } };
#pragma unroll
            for (int nt = 0; nt < 2; nt++) {
                mma_bf16(acco[0][nt], ah0, bh[nt]);
                mma_bf16(acco[1][nt], ah1, bh[nt]);
                mma_bf16(acco[0][nt], al0, bh[nt]);
                mma_bf16(acco[1][nt], al1, bh[nt]);
                mma_bf16(acco[0][nt], ah0, bl[nt]);
                mma_bf16(acco[1][nt], ah1, bl[nt]);
            }
        }
    }

    float* raw = (float*)(smem + OC_RAW);
    const int g = lane >> 2, tig = lane & 3;
#pragma unroll
    for (int mt = 0; mt < 2; mt++)
#pragma unroll
        for (int nt = 0; nt < 2; nt++) {
            int r0 = mt * 16 + g;
            int px0 = n0 + nt * 8 + 2 * tig;
            raw[px0 * 33 + r0]           = acco[mt][nt][0];
            raw[(px0 + 1) * 33 + r0]     = acco[mt][nt][1];
            raw[px0 * 33 + r0 + 8]       = acco[mt][nt][2];
            raw[(px0 + 1) * 33 + r0 + 8] = acco[mt][nt][3];
        }
    __syncthreads();
    if (tid < 128) {
        int px = tid;
        float a[27];
#pragma unroll
        for (int k = 0; k < 27; k++) a[k] = raw[px * 33 + k] + b_off[k];
        float* o = &g_off[((size_t)(b * HH + y) * WW + px) * 27];
#pragma unroll
        for (int k = 0; k < 9; k++) {
            int ky = k / 3, kx = k - ky * 3;
            o[k]      = a[2 * k]     + (float)(y + ky - 1);
            o[9 + k]  = a[2 * k + 1] + (float)(px + kx - 1);
            o[18 + k] = 1.f / (1.f + __expf(-a[18 + k]));
        }
    }
}

// ---------------- Kernel: warp-specialized deform GEMM v3 (coalesced sampler) ----------------
// 384 threads: warps 0-3 consumers (32co x 64px each), warps 4-11 samplers.
// Sampler warp = 8 pixels; per pixel, all 32 lanes load one 512B corner row together.
// smem: A[2] 2x64K | B[2] 2x32K | ofs 7K = ~199 KB, 1 block/SM.
#define OFF_A   0
#define OFF_B   131072
#define OFF_OFS 196608
#define SMEM_BYTES (OFF_OFS + 64*28*4)

__global__ __launch_bounds__(384) void k_main(const float* __restrict__ b_dc,
                                              float* __restrict__ out) {
    extern __shared__ __align__(1024) char smem[];
    const uint32_t sbase = smem_u32(smem);
    const int tid = threadIdx.x, lane = tid & 31, warp = tid >> 5;
    const int b = blockIdx.x >> 8;
    const int rem = blockIdx.x & 255;
    const int y = rem >> 1;
    const int px0 = (rem & 1) * 64;

    const int sub = lane >> 3, lr = lane & 7;
    const int kxa = sub >> 1, kxb = sub & 1;

    // --- consumer state (warps 0-3): warp tile 32co x 64px ---
    const int mrow = warp * 32;
    const uint32_t aoff0 = (uint32_t)(mrow + (sub & 1) * 8 + lr) * 256;
    const uint32_t aoff1 = aoff0 + 16 * 256;
    const uint32_t brow  = (uint32_t)((sub >> 1) * 8 + lr) * 256;

    // --- sampler state (warps 4-11): warp handles 8 pixels ---
    const int stid = tid - 128;                  // 0..255 for samplers
    const int wpx0 = (warp - 4) * 8;             // first pixel of this sampler warp
    const float* base_b = g_nhwc + (size_t)b * HW * CIN;
    float* s_ofs = (float*)(smem + OFF_OFS);     // [64 px][28]

    float acc[2][8][4];
    if (warp < 4) {
#pragma unroll
        for (int i = 0; i < 2; i++)
#pragma unroll
            for (int j = 0; j < 8; j++)
#pragma unroll
                for (int k = 0; k < 4; k++) acc[i][j][k] = 0.f;
    }

    // stage offsets for this block's 64 pixels into smem (once)
    {
        const float* gsrc = &g_off[((size_t)(b * HH + y) * WW + px0) * 27];
        for (int e = tid; e < 64 * 27; e += 384) {
            int p = e / 27, k = e - p * 27;
            s_ofs[p * 28 + k] = gsrc[p * 27 + k];
        }
    }

    // sampler: warp-coalesced bilinear fill of B[BUF] for tap TT
#define STAGE_B(TT, BUF) do {                                                               \
        uint32_t bb = sbase + OFF_B + (uint32_t)(BUF) * 32768;                              \
        _Pragma("unroll")                                                                   \
        for (int pp = 0; pp < 8; pp++) {                                                    \
            int p = wpx0 + pp;                                                              \
            const float* o = s_ofs + p * 28;                                                \
            float py = o[TT], pxx = o[9 + (TT)], m = o[18 + (TT)];                          \
            float y0f = floorf(py), x0f = floorf(pxx);                                      \
            float ly = py - y0f, lx = pxx - x0f;                                            \
            int y0 = (int)y0f, x0 = (int)x0f, y1 = y0 + 1, x1 = x0 + 1;                     \
            float f00 = (y0 >= 0 && y0 < HH && x0 >= 0 && x0 < WW) ? 1.f : 0.f;             \
            float f01 = (y0 >= 0 && y0 < HH && x1 >= 0 && x1 < WW) ? 1.f : 0.f;             \
            float f10 = (y1 >= 0 && y1 < HH && x0 >= 0 && x0 < WW) ? 1.f : 0.f;             \
            float f11 = (y1 >= 0 && y1 < HH && x1 >= 0 && x1 < WW) ? 1.f : 0.f;             \
            const unsigned long long w00d = dup2((1.f - ly) * (1.f - lx) * m * f00);        \
            const unsigned long long w01d = dup2((1.f - ly) * lx         * m * f01);        \
            const unsigned long long w10d = dup2(ly         * (1.f - lx) * m * f10);        \
            const unsigned long long w11d = dup2(ly         * lx         * m * f11);        \
            int y0c = min(max(y0, 0), HH - 1), x0c = min(max(x0, 0), WW - 1);               \
            int y1c = min(max(y1, 0), HH - 1), x1c = min(max(x1, 0), WW - 1);               \
            int ci = lane * 4;                                                              \
            ulonglong2 A2 = *(const ulonglong2*)(base_b + ((size_t)(y0c * WW + x0c)) * CIN + ci); \
            ulonglong2 C2 = *(const ulonglong2*)(base_b + ((size_t)(y0c * WW + x1c)) * CIN + ci); \
            ulonglong2 D2 = *(const ulonglong2*)(base_b + ((size_t)(y1c * WW + x0c)) * CIN + ci); \
            ulonglong2 E2 = *(const ulonglong2*)(base_b + ((size_t)(y1c * WW + x1c)) * CIN + ci); \
            unsigned long long v01 = 0ULL, v23 = 0ULL;                                      \
            fma2(v01, A2.x, w00d); fma2(v01, C2.x, w01d); fma2(v01, D2.x, w10d); fma2(v01, E2.x, w11d); \
            fma2(v23, A2.y, w00d); fma2(v23, C2.y, w01d); fma2(v23, D2.y, w10d); fma2(v23, E2.y, w11d); \
            float2 f01v = unpk(v01), f23v = unpk(v23);                                      \
            uint32_t hi01 = cvt_bf2(f01v.y, f01v.x);                                       \
            uint32_t hi23 = cvt_bf2(f23v.y, f23v.x);                                       \
            float l0 = f01v.x - __uint_as_float(hi01 << 16);                                \
            float l1 = f01v.y - __uint_as_float(hi01 & 0xFFFF0000u);                        \
            float l2 = f23v.x - __uint_as_float(hi23 << 16);                                \
            float l3 = f23v.y - __uint_as_float(hi23 & 0xFFFF0000u);                        \
            uint32_t lo01 = cvt_bf2(l1, l0);                                                \
            uint32_t lo23 = cvt_bf2(l3, l2);                                                \
            uint32_t a0 = tswz(p, ci);                                                      \
            *(unsigned long long*)(smem + ((bb - sbase) + a0))         = ((unsigned long long)hi23 << 32) | hi01; \
            *(unsigned long long*)(smem + ((bb - sbase) + 16384 + a0)) = ((unsigned long long)lo23 << 32) | lo01; \
        }                                                                                   \
    } while (0)

    // sampler A-staging: 64KB into A[BUF], 256 sampler threads x 16 chunks
#define STAGE_A(TT, BUF) do {                                                               \
        const char* asrc = (const char*)(g_wtA + (size_t)(TT) * 32768);                     \
        uint32_t adst = sbase + OFF_A + (uint32_t)(BUF) * 65536;                            \
        _Pragma("unroll")                                                                   \
        for (int e = 0; e < 16; e++)                                                        \
            cpasync16(adst + (uint32_t)(stid + e * 256) * 16, asrc + (size_t)(stid + e * 256) * 16); \
    } while (0)

    __syncthreads();   // s_ofs ready

    // prologue: samplers stage A[0] + fill B[0]
    if (warp >= 4) {
        STAGE_A(0, 0);
        STAGE_B(0, 0);
        CPASYNC_WAIT();
    }
    __syncthreads();

    for (int t = 0; t < 9; t++) {
        const int cur = t & 1;
        if (warp < 4) {
            const uint32_t sAh = sbase + OFF_A + (uint32_t)cur * 65536;
            const uint32_t sAl = sAh + 32768;
            const uint32_t sBh = sbase + OFF_B + (uint32_t)cur * 32768;
            const uint32_t sBl = sBh + 16384;
#pragma unroll
            for (int ks = 0; ks < 8; ks++) {
                uint32_t ca = (uint32_t)(((2 * ks + kxa) ^ lr) << 4);
                uint32_t cb = (uint32_t)(((2 * ks + kxb) ^ lr) << 4);
                uint32_t ah0[4], ah1[4], al0[4], al1[4];
                ldmx4(ah0, sAh + aoff0 + ca);
                ldmx4(ah1, sAh + aoff1 + ca);
                ldmx4(al0, sAl + aoff0 + ca);
                ldmx4(al1, sAl + aoff1 + ca);
#pragma unroll
                for (int q = 0; q < 4; q++) {
                    uint32_t badr = brow + (uint32_t)(q * 16) * 256 + cb;
                    uint32_t qh[4], ql[4];
                    ldmx4(qh, sBh + badr);
                    ldmx4(ql, sBl + badr);
#pragma unroll
                    for (int j = 0; j < 2; j++) {
                        int nt = 2 * q + j;
                        uint32_t bh[2] = { qh[2 * j], qh[2 * j + 1] };
                        uint32_t bl[2] = { ql[2 * j], ql[2 * j + 1] };
                        mma_bf16(acc[0][nt], ah0, bh);
                        mma_bf16(acc[1][nt], ah1, bh);
                        mma_bf16(acc[0][nt], al0, bh);
                        mma_bf16(acc[1][nt], al1, bh);
                        mma_bf16(acc[0][nt], ah0, bl);
                        mma_bf16(acc[1][nt], ah1, bl);
                    }
                }
            }
        } else if (t < 8) {
            const int nxt = (t + 1) & 1;
            STAGE_A(t + 1, nxt);
            STAGE_B(t + 1, nxt);
            CPASYNC_WAIT();
        }
        __syncthreads();
    }

    // epilogue: consumers write d-frags -> gmem NCHW with bias
    if (warp < 4) {
        const int g = lane >> 2, tig = lane & 3;
#pragma unroll
        for (int mt = 0; mt < 2; mt++) {
            int coA = mrow + mt * 16 + g;
            int coB = coA + 8;
            float bA = b_dc[coA], bB2 = b_dc[coB];
            float* oA = out + ((size_t)(b * COUT + coA) * HH + y) * WW + px0;
            float* oB = out + ((size_t)(b * COUT + coB) * HH + y) * WW + px0;
#pragma unroll
            for (int nt = 0; nt < 8; nt++) {
                int px = nt * 8 + 2 * tig;
                float2 vA = make_float2(acc[mt][nt][0] + bA,  acc[mt][nt][1] + bA);
                float2 vB = make_float2(acc[mt][nt][2] + bB2, acc[mt][nt][3] + bB2);
                *(float2*)(oA + px) = vA;
                *(float2*)(oB + px) = vB;
            }
        }
    }
#undef STAGE_B
#undef STAGE_A
}

// ---------------- launch ----------------
extern "C" void kernel_launch(void* const* d_in, const int* in_sizes, int n_in,
                              void* d_out, int out_size) {
    const float* inp   = (const float*)d_in[0];
    const float* feat  = (const float*)d_in[1];
    const float* w_off = (const float*)d_in[2];
    const float* b_off = (const float*)d_in[3];
    const float* w_dc  = (const float*)d_in[4];
    const float* b_dc  = (const float*)d_in[5];
    float* out = (float*)d_out;

    static bool attr_set = false;
    if (!attr_set) {
        cudaFuncSetAttribute(k_main, cudaFuncAttributeMaxDynamicSharedMemorySize, SMEM_BYTES);
        cudaFuncSetAttribute(k_offset_tc, cudaFuncAttributeMaxDynamicSharedMemorySize, OC_SMEM);
        attr_set = true;
    }

    k_transposeF<<<dim3(HW / 32, CIN / 32, BB), dim3(32, 8)>>>(feat);
    k_prep_woffA<<<(9 * 4096 + 255) / 256, 256>>>(w_off);
    k_transpose<<<dim3(HW / 32, CIN / 32, BB), dim3(32, 8)>>>(inp);
    k_prep_wtA<<<(9 * 16384 + 255) / 256, 256>>>(w_dc);
    k_offset_tc<<<BB * HH, 256, OC_SMEM>>>(b_off);
    k_main<<<BB * HH * 2, 384, SMEM_BYTES>>>(b_dc, out);
}

// round 15
// speedup vs baseline: 1.4597x; 1.0213x over previous
#include <cuda_runtime.h>
#include <cuda_bf16.h>
#include <stdint.h>
#include <math.h>

#define BB   4
#define CIN  128
#define COUT 128
#define HH   128
#define WW   128
#define HW   (HH*WW)

// ---------------- global scratch ----------------
__device__ float g_nhwc[BB*HW*CIN];                        // inp NHWC fp32
__device__ float g_off [BB*HW*27];                         // py[9], px[9], mask[9]
__device__ __align__(16) __nv_bfloat16 g_fh[BB*HW*CIN];    // feat NHWC bf16 hi
__device__ __align__(16) __nv_bfloat16 g_fl[BB*HW*CIN];    // feat NHWC bf16 lo
__device__ __align__(16) __nv_bfloat16 g_wtA[9*2*16384];   // per tap: swizzled [co][ci] hi+lo (deform A)
__device__ __align__(16) __nv_bfloat16 g_woffA[9*2*4096];  // per tap: swizzled [32oc pad][ci] hi+lo (offset A)

// ---------------- helpers ----------------
__device__ __forceinline__ uint32_t smem_u32(const void* p) {
    uint32_t a;
    asm("{ .reg .u64 t; cvta.to.shared.u64 t, %1; cvt.u32.u64 %0, t; }" : "=r"(a) : "l"(p));
    return a;
}
__device__ __forceinline__ void ldmx4(uint32_t* r, uint32_t addr) {
    asm volatile("ldmatrix.sync.aligned.m8n8.x4.shared.b16 {%0,%1,%2,%3}, [%4];"
        : "=r"(r[0]), "=r"(r[1]), "=r"(r[2]), "=r"(r[3]) : "r"(addr));
}
__device__ __forceinline__ void mma_bf16(float* d, const uint32_t* a, const uint32_t* b) {
    asm volatile("mma.sync.aligned.m16n8k16.row.col.f32.bf16.bf16.f32 "
        "{%0,%1,%2,%3}, {%4,%5,%6,%7}, {%8,%9}, {%0,%1,%2,%3};"
        : "+f"(d[0]), "+f"(d[1]), "+f"(d[2]), "+f"(d[3])
        : "r"(a[0]), "r"(a[1]), "r"(a[2]), "r"(a[3]), "r"(b[0]), "r"(b[1]));
}
__device__ __forceinline__ void cpasync16(uint32_t dst, const void* src) {
    asm volatile("cp.async.cg.shared.global [%0], [%1], 16;" :: "r"(dst), "l"(src));
}
#define CPASYNC_WAIT() asm volatile("cp.async.wait_all;" ::: "memory")

__device__ __forceinline__ void fma2(unsigned long long &d, unsigned long long a, unsigned long long b) {
    asm("fma.rn.f32x2 %0, %1, %2, %0;" : "+l"(d) : "l"(a), "l"(b));
}
__device__ __forceinline__ unsigned long long dup2(float x) {
    unsigned long long r; asm("mov.b64 %0, {%1, %1};" : "=l"(r) : "f"(x)); return r;
}
__device__ __forceinline__ float2 unpk(unsigned long long v) {
    float2 r; asm("mov.b64 {%0, %1}, %2;" : "=f"(r.x), "=f"(r.y) : "l"(v)); return r;
}
// packs: a -> upper 16, b -> lower 16
__device__ __forceinline__ uint32_t cvt_bf2(float hi, float lo) {
    uint32_t d; asm("cvt.rn.bf16x2.f32 %0, %1, %2;" : "=r"(d) : "f"(hi), "f"(lo)); return d;
}

// swizzled byte offset in a [rows][128 cols-bf16] tile, pitch 256 B
__device__ __forceinline__ uint32_t tswz(int row, int ci) {
    return (uint32_t)(row * 256 + ((((ci >> 3) ^ (row & 7)) << 4) | ((ci & 7) * 2)));
}

// ---------------- Kernel: NCHW -> NHWC fp32 transpose of inp ----------------
__global__ void k_transpose(const float* __restrict__ inp) {
    __shared__ float tile[32][33];
    int b = blockIdx.z, c0 = blockIdx.y * 32, p0 = blockIdx.x * 32;
    int tx = threadIdx.x, ty = threadIdx.y;
#pragma unroll
    for (int i = 0; i < 4; i++)
        tile[ty + i * 8][tx] = inp[(b * CIN + c0 + ty + i * 8) * HW + p0 + tx];
    __syncthreads();
#pragma unroll
    for (int i = 0; i < 4; i++)
        g_nhwc[((size_t)b * HW + p0 + ty + i * 8) * CIN + c0 + tx] = tile[tx][ty + i * 8];
}

// ---------------- Kernel: NCHW -> NHWC bf16 hi/lo transpose of feat ----------------
__global__ void k_transposeF(const float* __restrict__ feat) {
    __shared__ float tile[32][33];
    int b = blockIdx.z, c0 = blockIdx.y * 32, p0 = blockIdx.x * 32;
    int tx = threadIdx.x, ty = threadIdx.y;
#pragma unroll
    for (int i = 0; i < 4; i++)
        tile[ty + i * 8][tx] = feat[(b * CIN + c0 + ty + i * 8) * HW + p0 + tx];
    __syncthreads();
#pragma unroll
    for (int i = 0; i < 4; i++) {
        float w = tile[tx][ty + i * 8];
        __nv_bfloat16 h = __float2bfloat16(w);
        __nv_bfloat16 l = __float2bfloat16(w - __bfloat162float(h));
        size_t idx = ((size_t)b * HW + p0 + ty + i * 8) * CIN + c0 + tx;
        g_fh[idx] = h;
        g_fl[idx] = l;
    }
}

// ---------------- Kernel: w_dc -> swizzled bf16 hi/lo A tiles [co][ci] ----------------
__global__ void k_prep_wtA(const float* __restrict__ w_dc) {
    int idx = blockIdx.x * blockDim.x + threadIdx.x;
    if (idx >= 9 * 16384) return;
    int t  = idx >> 14;
    int r  = idx & 16383;
    int co = r >> 7;
    int ci = r & 127;
    float w = w_dc[(co * CIN + ci) * 9 + t];
    __nv_bfloat16 h = __float2bfloat16(w);
    __nv_bfloat16 l = __float2bfloat16(w - __bfloat162float(h));
    uint32_t e = tswz(co, ci) >> 1;
    g_wtA[t * 32768 + e]         = h;
    g_wtA[t * 32768 + 16384 + e] = l;
}

// ---------------- Kernel: w_off -> swizzled bf16 hi/lo A tiles [32oc pad][ci] ----------------
__global__ void k_prep_woffA(const float* __restrict__ w_off) {
    int idx = blockIdx.x * blockDim.x + threadIdx.x;
    if (idx >= 9 * 4096) return;
    int t  = idx >> 12;
    int r  = idx & 4095;
    int oc = r >> 7;
    int ci = r & 127;
    float w = (oc < 27) ? w_off[(oc * CIN + ci) * 9 + t] : 0.f;
    __nv_bfloat16 h = __float2bfloat16(w);
    __nv_bfloat16 l = __float2bfloat16(w - __bfloat162float(h));
    uint32_t e = tswz(oc, ci) >> 1;
    g_woffA[t * 8192 + e]        = h;
    g_woffA[t * 8192 + 4096 + e] = l;
}

// ---------------- Kernel: offset conv v2 — warp-specialized pipeline ----------------
// 384 threads: warps 0-3 consumers (M=32, n=32 px each), warps 4-11 producers.
// smem: A[2] 2x16K @0 | B[2] 2x64K @32768 | raw 17K @163840 = ~177 KB, 1 block/SM.
#define OC_A(buf)   ((uint32_t)(buf) * 16384)
#define OC_B(buf)   (32768u + (uint32_t)(buf) * 65536)
#define OC_RAW      163840
#define OC_SMEM     (OC_RAW + 128*33*4)

__global__ __launch_bounds__(384) void k_offset_tc(const float* __restrict__ b_off) {
    extern __shared__ __align__(1024) char smem[];
    const uint32_t sbase = smem_u32(smem);
    const int tid = threadIdx.x, lane = tid & 31, warp = tid >> 5;
    const int b = blockIdx.x >> 7, y = blockIdx.x & 127;

    const int sub = lane >> 3, lr = lane & 7;
    const int kxa = sub >> 1, kxb = sub & 1;

    // --- consumer geometry (warps 0-3): M=32, warp n-tile = 32 px ---
    const int npx0 = warp * 32;
    const uint32_t aoA0 = (uint32_t)((sub & 1) * 8 + lr) * 256;
    const uint32_t aoA1 = aoA0 + 16 * 256;
    const uint32_t boff0 = (uint32_t)(npx0 + (sub >> 1) * 8 + lr) * 256;
    const uint32_t boff1 = boff0 + 16 * 256;

    // --- producer roles (warps 4-11): 256 threads, 2 per pixel ---
    const int stid = tid - 128;
    const int sp   = (stid >= 0 ? stid : 0) >> 1;       // pixel 0..127
    const int ci0  = ((stid >= 0 ? stid : 0) & 1) * 64;

    float acc[2][4][4];
    if (warp < 4) {
#pragma unroll
        for (int i = 0; i < 2; i++)
#pragma unroll
            for (int j = 0; j < 4; j++)
#pragma unroll
                for (int k = 0; k < 4; k++) acc[i][j][k] = 0.f;
    }

#define OC_STAGE(TT, BUF) do {                                                              \
        const char* asrc = (const char*)(g_woffA + (size_t)(TT) * 8192);                    \
        uint32_t adst = sbase + OC_A(BUF);                                                  \
        _Pragma("unroll")                                                                   \
        for (int e = 0; e < 4; e++)                                                         \
            cpasync16(adst + (uint32_t)(stid + e * 256) * 16, asrc + (size_t)(stid + e * 256) * 16); \
        int ky = (TT) / 3, kx = (TT) - ky * 3;                                              \
        int yy = y + ky - 1, xx = sp + kx - 1;                                              \
        bool ok = (yy >= 0) & (yy < HH) & (xx >= 0) & (xx < WW);                            \
        int yyc = min(max(yy, 0), HH - 1), xxc = min(max(xx, 0), WW - 1);                   \
        size_t pbase = ((size_t)(b * HW + yyc * WW + xxc)) * CIN + ci0;                     \
        const uint4* fh = (const uint4*)(g_fh + pbase);                                     \
        const uint4* fl = (const uint4*)(g_fl + pbase);                                     \
        const uint4 z4 = make_uint4(0, 0, 0, 0);                                            \
        _Pragma("unroll")                                                                   \
        for (int j = 0; j < 8; j++) {                                                       \
            uint4 vh = ok ? fh[j] : z4;                                                     \
            uint4 vl = ok ? fl[j] : z4;                                                     \
            uint32_t a0 = tswz(sp, ci0 + 8 * j);                                            \
            *(uint4*)(smem + OC_B(BUF) + a0)         = vh;                                  \
            *(uint4*)(smem + OC_B(BUF) + 32768 + a0) = vl;                                  \
        }                                                                                   \
        CPASYNC_WAIT();                                                                     \
    } while (0)

    // prologue: producers stage tap 0 into buffer 0
    if (warp >= 4) { OC_STAGE(0, 0); }
    __syncthreads();

    for (int t = 0; t < 9; t++) {
        const int cur = t & 1;
        if (warp < 4) {
            const uint32_t sAh = sbase + OC_A(cur), sAl = sAh + 8192;
            const uint32_t sBh = sbase + OC_B(cur), sBl = sBh + 32768;
#pragma unroll
            for (int ks = 0; ks < 8; ks++) {
                uint32_t ca = (uint32_t)(((2 * ks + kxa) ^ lr) << 4);
                uint32_t cb = (uint32_t)(((2 * ks + kxb) ^ lr) << 4);
                uint32_t ah0[4], ah1[4], al0[4], al1[4];
                ldmx4(ah0, sAh + aoA0 + ca);
                ldmx4(ah1, sAh + aoA1 + ca);
                ldmx4(al0, sAl + aoA0 + ca);
                ldmx4(al1, sAl + aoA1 + ca);
                uint32_t bh[4][2], bl[4][2], q[4];
                ldmx4(q, sBh + boff0 + cb); bh[0][0]=q[0]; bh[0][1]=q[1]; bh[1][0]=q[2]; bh[1][1]=q[3];
                ldmx4(q, sBh + boff1 + cb); bh[2][0]=q[0]; bh[2][1]=q[1]; bh[3][0]=q[2]; bh[3][1]=q[3];
                ldmx4(q, sBl + boff0 + cb); bl[0][0]=q[0]; bl[0][1]=q[1]; bl[1][0]=q[2]; bl[1][1]=q[3];
                ldmx4(q, sBl + boff1 + cb); bl[2][0]=q[0]; bl[2][1]=q[1]; bl[3][0]=q[2]; bl[3][1]=q[3];
#pragma unroll
                for (int nt = 0; nt < 4; nt++) {
                    mma_bf16(acc[0][nt], ah0, bh[nt]);
                    mma_bf16(acc[1][nt], ah1, bh[nt]);
                    mma_bf16(acc[0][nt], al0, bh[nt]);
                    mma_bf16(acc[1][nt], al1, bh[nt]);
                    mma_bf16(acc[0][nt], ah0, bl[nt]);
                    mma_bf16(acc[1][nt], ah1, bl[nt]);
                }
            }
        } else if (t < 8) {
            OC_STAGE(t + 1, (t + 1) & 1);
        }
        __syncthreads();
    }

    // consumers write d-frags -> raw [px][33]
    float* raw = (float*)(smem + OC_RAW);
    if (warp < 4) {
        const int g = lane >> 2, tig = lane & 3;
#pragma unroll
        for (int mt = 0; mt < 2; mt++)
#pragma unroll
            for (int nt = 0; nt < 4; nt++) {
                int r0 = mt * 16 + g;
                int px0 = npx0 + nt * 8 + 2 * tig;
                raw[px0 * 33 + r0]           = acc[mt][nt][0];
                raw[(px0 + 1) * 33 + r0]     = acc[mt][nt][1];
                raw[px0 * 33 + r0 + 8]       = acc[mt][nt][2];
                raw[(px0 + 1) * 33 + r0 + 8] = acc[mt][nt][3];
            }
    }
    __syncthreads();
    // transform -> g_off (one thread per pixel)
    if (tid < 128) {
        int px = tid;
        float a[27];
#pragma unroll
        for (int k = 0; k < 27; k++) a[k] = raw[px * 33 + k] + b_off[k];
        float* o = &g_off[((size_t)(b * HH + y) * WW + px) * 27];
#pragma unroll
        for (int k = 0; k < 9; k++) {
            int ky = k / 3, kx = k - ky * 3;
            o[k]      = a[2 * k]     + (float)(y + ky - 1);
            o[9 + k]  = a[2 * k + 1] + (float)(px + kx - 1);
            o[18 + k] = 1.f / (1.f + __expf(-a[18 + k]));
        }
    }
#undef OC_STAGE
}

// ---------------- Kernel: warp-specialized deform GEMM v3 (R14, verified) ----------------
// 384 threads: warps 0-3 consumers (32co x 64px each), warps 4-11 samplers.
#define OFF_A   0
#define OFF_B   131072
#define OFF_OFS 196608
#define SMEM_BYTES (OFF_OFS + 64*28*4)

__global__ __launch_bounds__(384) void k_main(const float* __restrict__ b_dc,
                                              float* __restrict__ out) {
    extern __shared__ __align__(1024) char smem[];
    const uint32_t sbase = smem_u32(smem);
    const int tid = threadIdx.x, lane = tid & 31, warp = tid >> 5;
    const int b = blockIdx.x >> 8;
    const int rem = blockIdx.x & 255;
    const int y = rem >> 1;
    const int px0 = (rem & 1) * 64;

    const int sub = lane >> 3, lr = lane & 7;
    const int kxa = sub >> 1, kxb = sub & 1;

    // --- consumer state (warps 0-3): warp tile 32co x 64px ---
    const int mrow = warp * 32;
    const uint32_t aoff0 = (uint32_t)(mrow + (sub & 1) * 8 + lr) * 256;
    const uint32_t aoff1 = aoff0 + 16 * 256;
    const uint32_t brow  = (uint32_t)((sub >> 1) * 8 + lr) * 256;

    // --- sampler state (warps 4-11): warp handles 8 pixels ---
    const int stid = tid - 128;
    const int wpx0 = (warp - 4) * 8;
    const float* base_b = g_nhwc + (size_t)b * HW * CIN;
    float* s_ofs = (float*)(smem + OFF_OFS);

    float acc[2][8][4];
    if (warp < 4) {
#pragma unroll
        for (int i = 0; i < 2; i++)
#pragma unroll
            for (int j = 0; j < 8; j++)
#pragma unroll
                for (int k = 0; k < 4; k++) acc[i][j][k] = 0.f;
    }

    {
        const float* gsrc = &g_off[((size_t)(b * HH + y) * WW + px0) * 27];
        for (int e = tid; e < 64 * 27; e += 384) {
            int p = e / 27, k = e - p * 27;
            s_ofs[p * 28 + k] = gsrc[p * 27 + k];
        }
    }

#define STAGE_B(TT, BUF) do {                                                               \
        uint32_t bb = sbase + OFF_B + (uint32_t)(BUF) * 32768;                              \
        _Pragma("unroll")                                                                   \
        for (int pp = 0; pp < 8; pp++) {                                                    \
            int p = wpx0 + pp;                                                              \
            const float* o = s_ofs + p * 28;                                                \
            float py = o[TT], pxx = o[9 + (TT)], m = o[18 + (TT)];                          \
            float y0f = floorf(py), x0f = floorf(pxx);                                      \
            float ly = py - y0f, lx = pxx - x0f;                                            \
            int y0 = (int)y0f, x0 = (int)x0f, y1 = y0 + 1, x1 = x0 + 1;                     \
            float f00 = (y0 >= 0 && y0 < HH && x0 >= 0 && x0 < WW) ? 1.f : 0.f;             \
            float f01 = (y0 >= 0 && y0 < HH && x1 >= 0 && x1 < WW) ? 1.f : 0.f;             \
            float f10 = (y1 >= 0 && y1 < HH && x0 >= 0 && x0 < WW) ? 1.f : 0.f;             \
            float f11 = (y1 >= 0 && y1 < HH && x1 >= 0 && x1 < WW) ? 1.f : 0.f;             \
            const unsigned long long w00d = dup2((1.f - ly) * (1.f - lx) * m * f00);        \
            const unsigned long long w01d = dup2((1.f - ly) * lx         * m * f01);        \
            const unsigned long long w10d = dup2(ly         * (1.f - lx) * m * f10);        \
            const unsigned long long w11d = dup2(ly         * lx         * m * f11);        \
            int y0c = min(max(y0, 0), HH - 1), x0c = min(max(x0, 0), WW - 1);               \
            int y1c = min(max(y1, 0), HH - 1), x1c = min(max(x1, 0), WW - 1);               \
            int ci = lane * 4;                                                              \
            ulonglong2 A2 = *(const ulonglong2*)(base_b + ((size_t)(y0c * WW + x0c)) * CIN + ci); \
            ulonglong2 C2 = *(const ulonglong2*)(base_b + ((size_t)(y0c * WW + x1c)) * CIN + ci); \
            ulonglong2 D2 = *(const ulonglong2*)(base_b + ((size_t)(y1c * WW + x0c)) * CIN + ci); \
            ulonglong2 E2 = *(const ulonglong2*)(base_b + ((size_t)(y1c * WW + x1c)) * CIN + ci); \
            unsigned long long v01 = 0ULL, v23 = 0ULL;                                      \
            fma2(v01, A2.x, w00d); fma2(v01, C2.x, w01d); fma2(v01, D2.x, w10d); fma2(v01, E2.x, w11d); \
            fma2(v23, A2.y, w00d); fma2(v23, C2.y, w01d); fma2(v23, D2.y, w10d); fma2(v23, E2.y, w11d); \
            float2 f01v = unpk(v01), f23v = unpk(v23);                                      \
            uint32_t hi01 = cvt_bf2(f01v.y, f01v.x);                                       \
            uint32_t hi23 = cvt_bf2(f23v.y, f23v.x);                                       \
            float l0 = f01v.x - __uint_as_float(hi01 << 16);                                \
            float l1 = f01v.y - __uint_as_float(hi01 & 0xFFFF0000u);                        \
            float l2 = f23v.x - __uint_as_float(hi23 << 16);                                \
            float l3 = f23v.y - __uint_as_float(hi23 & 0xFFFF0000u);                        \
            uint32_t lo01 = cvt_bf2(l1, l0);                                                \
            uint32_t lo23 = cvt_bf2(l3, l2);                                                \
            uint32_t a0 = tswz(p, ci);                                                      \
            *(unsigned long long*)(smem + ((bb - sbase) + a0))         = ((unsigned long long)hi23 << 32) | hi01; \
            *(unsigned long long*)(smem + ((bb - sbase) + 16384 + a0)) = ((unsigned long long)lo23 << 32) | lo01; \
        }                                                                                   \
    } while (0)

#define STAGE_A(TT, BUF) do {                                                               \
        const char* asrc = (const char*)(g_wtA + (size_t)(TT) * 32768);                     \
        uint32_t adst = sbase + OFF_A + (uint32_t)(BUF) * 65536;                            \
        _Pragma("unroll")                                                                   \
        for (int e = 0; e < 16; e++)                                                        \
            cpasync16(adst + (uint32_t)(stid + e * 256) * 16, asrc + (size_t)(stid + e * 256) * 16); \
    } while (0)

    __syncthreads();   // s_ofs ready

    if (warp >= 4) {
        STAGE_A(0, 0);
        STAGE_B(0, 0);
        CPASYNC_WAIT();
    }
    __syncthreads();

    for (int t = 0; t < 9; t++) {
        const int cur = t & 1;
        if (warp < 4) {
            const uint32_t sAh = sbase + OFF_A + (uint32_t)cur * 65536;
            const uint32_t sAl = sAh + 32768;
            const uint32_t sBh = sbase + OFF_B + (uint32_t)cur * 32768;
            const uint32_t sBl = sBh + 16384;
#pragma unroll
            for (int ks = 0; ks < 8; ks++) {
                uint32_t ca = (uint32_t)(((2 * ks + kxa) ^ lr) << 4);
                uint32_t cb = (uint32_t)(((2 * ks + kxb) ^ lr) << 4);
                uint32_t ah0[4], ah1[4], al0[4], al1[4];
                ldmx4(ah0, sAh + aoff0 + ca);
                ldmx4(ah1, sAh + aoff1 + ca);
                ldmx4(al0, sAl + aoff0 + ca);
                ldmx4(al1, sAl + aoff1 + ca);
#pragma unroll
                for (int q = 0; q < 4; q++) {
                    uint32_t badr = brow + (uint32_t)(q * 16) * 256 + cb;
                    uint32_t qh[4], ql[4];
                    ldmx4(qh, sBh + badr);
                    ldmx4(ql, sBl + badr);
#pragma unroll
                    for (int j = 0; j < 2; j++) {
                        int nt = 2 * q + j;
                        uint32_t bh[2] = { qh[2 * j], qh[2 * j + 1] };
                        uint32_t bl[2] = { ql[2 * j], ql[2 * j + 1] };
                        mma_bf16(acc[0][nt], ah0, bh);
                        mma_bf16(acc[1][nt], ah1, bh);
                        mma_bf16(acc[0][nt], al0, bh);
                        mma_bf16(acc[1][nt], al1, bh);
                        mma_bf16(acc[0][nt], ah0, bl);
                        mma_bf16(acc[1][nt], ah1, bl);
                    }
                }
            }
        } else if (t < 8) {
            const int nxt = (t + 1) & 1;
            STAGE_A(t + 1, nxt);
            STAGE_B(t + 1, nxt);
            CPASYNC_WAIT();
        }
        __syncthreads();
    }

    if (warp < 4) {
        const int g = lane >> 2, tig = lane & 3;
#pragma unroll
        for (int mt = 0; mt < 2; mt++) {
            int coA = mrow + mt * 16 + g;
            int coB = coA + 8;
            float bA = b_dc[coA], bB2 = b_dc[coB];
            float* oA = out + ((size_t)(b * COUT + coA) * HH + y) * WW + px0;
            float* oB = out + ((size_t)(b * COUT + coB) * HH + y) * WW + px0;
#pragma unroll
            for (int nt = 0; nt < 8; nt++) {
                int px = nt * 8 + 2 * tig;
                float2 vA = make_float2(acc[mt][nt][0] + bA,  acc[mt][nt][1] + bA);
                float2 vB = make_float2(acc[mt][nt][2] + bB2, acc[mt][nt][3] + bB2);
                *(float2*)(oA + px) = vA;
                *(float2*)(oB + px) = vB;
            }
        }
    }
#undef STAGE_B
#undef STAGE_A
}

// ---------------- launch ----------------
extern "C" void kernel_launch(void* const* d_in, const int* in_sizes, int n_in,
                              void* d_out, int out_size) {
    const float* inp   = (const float*)d_in[0];
    const float* feat  = (const float*)d_in[1];
    const float* w_off = (const float*)d_in[2];
    const float* b_off = (const float*)d_in[3];
    const float* w_dc  = (const float*)d_in[4];
    const float* b_dc  = (const float*)d_in[5];
    float* out = (float*)d_out;

    static bool attr_set = false;
    if (!attr_set) {
        cudaFuncSetAttribute(k_main, cudaFuncAttributeMaxDynamicSharedMemorySize, SMEM_BYTES);
        cudaFuncSetAttribute(k_offset_tc, cudaFuncAttributeMaxDynamicSharedMemorySize, OC_SMEM);
        attr_set = true;
    }

    k_transposeF<<<dim3(HW / 32, CIN / 32, BB), dim3(32, 8)>>>(feat);
    k_prep_woffA<<<(9 * 4096 + 255) / 256, 256>>>(w_off);
    k_transpose<<<dim3(HW / 32, CIN / 32, BB), dim3(32, 8)>>>(inp);
    k_prep_wtA<<<(9 * 16384 + 255) / 256, 256>>>(w_dc);
    k_offset_tc<<<BB * HH, 384, OC_SMEM>>>(b_off);
    k_main<<<BB * HH * 2, 384, SMEM_BYTES>>>(b_dc, out);
}